// round 6
// baseline (speedup 1.0000x reference)
#include <cuda_runtime.h>

#define NB 8
#define NA 65536
#define NG 32

// ---- pass1 (kA) config: lanes = gts, anchors serial ----
#define AW   64                // anchors per warp
#define WPB  8                 // warps per block
#define ABLK (AW * WPB)        // 512 anchors per block
#define NCH  (NA / ABLK)       // 128 blocks per batch

// ---- pass2 (kC) config ----
#define TPB 256
#define TAC 2
#define CHC (TPB * TAC)        // 512
#define NCHC (NA / CHC)        // 128
#define NBLK_C (NCHC * NB)     // 1024

// Scratch (no allocations allowed)
__device__ float    g_pi[NB * NG * NCH];     // partial best: inter
__device__ float    g_pu[NB * NG * NCH];     // partial best: union
__device__ unsigned g_px[NB * NG * NCH];     // partial best: anchor idx
__device__ unsigned g_mask[NB * NA];         // bit g set iff valid && iou>0.5 (+forced)
__device__ float    g_class;
__device__ float    g_coord[NB];
__device__ int      g_cnt[NB];
__device__ int      g_tick;

// ------------- Pass 1: lanes=g; SMEM anchors; ballot mask + serial argmax -------------
__global__ __launch_bounds__(256) void kA(
    const float* __restrict__ anchors,   // [A,4] xyxy
    const float* __restrict__ gt,        // [B,G,4] xywh
    const int*   __restrict__ nobj)      // [B]
{
    const int b    = blockIdx.y;
    const int tid  = threadIdx.x;
    const int lane = tid & 31, warp = tid >> 5;
    const int blk_base = blockIdx.x * ABLK;

    __shared__ float4 s_anc[ABLK];       // anchor xyxy
    __shared__ float  s_sa[ABLK];        // precomputed anchor area
    __shared__ float    s_bi[WPB][NG], s_bu[WPB][NG];
    __shared__ unsigned s_bx[WPB][NG];

    // preamble: stage this block's 512 anchors + areas into SMEM
#pragma unroll
    for (int k = 0; k < ABLK / 256; k++) {
        int i = tid + k * 256;
        float4 q = __ldg(((const float4*)anchors) + blk_base + i);
        s_anc[i] = q;
        s_sa[i]  = (q.z - q.x) * (q.w - q.y);
    }

    // per-lane gt constants (lane == g)
    float gx1, gy1, gx2, gy2, sg;
    {
        const int n = nobj[b];
        float4 q = ((const float4*)gt)[b * NG + lane];   // cx,cy,w,h
        float hx = q.z * 0.5f, hy = q.w * 0.5f;
        gx1 = q.x - hx; gy1 = q.y - hy;
        gx2 = q.x + hx; gy2 = q.y + hy;
        sg  = (gx2 - gx1) * (gy2 - gy1);
        if (lane >= n) {           // sentinel: zero overlap with any anchor
            gx1 = 3e9f; gx2 = 3e9f; gy1 = 0.f; gy2 = 1.f; sg = 0.f;
        }
    }
    __syncthreads();

    const int w_base = warp * AW;        // within-block anchor offset
    float bi = 0.f, bu = 1.f;
    unsigned bx = (unsigned)(blk_base + w_base);

    for (int a0 = w_base; a0 < w_base + AW; a0 += 4) {
        unsigned mw0, mw1, mw2, mw3;
#pragma unroll
        for (int k = 0; k < 4; k++) {
            float4 q = s_anc[a0 + k];            // LDS broadcast
            float sa = s_sa[a0 + k];             // LDS broadcast
            float lx = fmaxf(q.x, gx1), ly = fmaxf(q.y, gy1);
            float rx = fminf(q.z, gx2), ry = fminf(q.w, gy2);
            float w  = fmaxf(rx - lx, 0.f), h = fmaxf(ry - ly, 0.f);
            float inter = w * h;
            float u = (sa + sg) - inter;
            // exact sign of inter - 0.5u (single rounding; 0.5u exact)
            bool pos = fmaf(-0.5f, u, inter) > 0.f;
            unsigned bal = __ballot_sync(0xffffffffu, pos);
            if (k == 0) mw0 = bal; else if (k == 1) mw1 = bal;
            else if (k == 2) mw2 = bal; else mw3 = bal;
            // iou > best  <=>  inter*bu > bi*u  (u,bu > 0); strict > keeps
            // earliest (smallest) anchor index == jnp.argmax tie-break
            if (inter * bu > bi * u) {
                bi = inter; bu = u; bx = (unsigned)(blk_base + a0 + k);
            }
        }
        if (lane == 0)
            *(uint4*)&g_mask[b * NA + blk_base + a0] = make_uint4(mw0, mw1, mw2, mw3);
    }

    // block-level argmax reduce (8 warps, anchor-range ordered)
    s_bi[warp][lane] = bi; s_bu[warp][lane] = bu; s_bx[warp][lane] = bx;
    __syncthreads();
    if (tid < NG) {
        float Bi = s_bi[0][tid], Bu = s_bu[0][tid];
        unsigned Bx = s_bx[0][tid];
#pragma unroll
        for (int w = 1; w < WPB; w++) {
            float oi = s_bi[w][tid], ou = s_bu[w][tid];
            unsigned ox = s_bx[w][tid];
            float A = oi * Bu, C = Bi * ou;
            if (A > C || (A == C && ox < Bx)) { Bi = oi; Bu = ou; Bx = ox; }
        }
        int p = (b * NG + tid) * NCH + blockIdx.x;
        g_pi[p] = Bi; g_pu[p] = Bu; g_px[p] = Bx;
    }
}

// ------- Middle: reduce partials -> forced bits; zero accumulators -------
__global__ void kB(const int* __restrict__ nobj) {
    const int b = blockIdx.x;            // 8 blocks x 256 threads
    const int t = threadIdx.x;
    if (b == 0) {
        if (t == 0) { g_class = 0.f; g_tick = 0; }
        if (t < NB) { g_coord[t] = 0.f; g_cnt[t] = 0; }
    }
    const int g = t >> 3, s = t & 7;     // 8 threads per g, 16 chunks each
    float bi = 0.f, bu = 1.f; unsigned bx = 0xffffffffu;
    const int base = (b * NG + g) * NCH;
    for (int c = s * 16; c < s * 16 + 16; c++) {
        float oi = g_pi[base + c], ou = g_pu[base + c]; unsigned ox = g_px[base + c];
        float a = oi * bu, d = bi * ou;
        if (a > d || (a == d && ox < bx)) { bi = oi; bu = ou; bx = ox; }
    }
#pragma unroll
    for (int off = 4; off; off >>= 1) {
        float    oi = __shfl_down_sync(0xffffffffu, bi, off, 8);
        float    ou = __shfl_down_sync(0xffffffffu, bu, off, 8);
        unsigned ox = __shfl_down_sync(0xffffffffu, bx, off, 8);
        float a = oi * bu, d = bi * ou;
        if (a > d || (a == d && ox < bx)) { bi = oi; bu = ou; bx = ox; }
    }
    if (s == 0 && g < nobj[b])
        atomicOr(&g_mask[b * NA + bx], 1u << g);
}

// -------- Pass 2: class + coord losses, ticketed finalize --------
__global__ __launch_bounds__(TPB) void kC(
    const float* __restrict__ boxes,   // [B,A,4]
    const float* __restrict__ cls,     // [B,A,2]
    const float* __restrict__ gt,      // [B,G,4]
    float* __restrict__ out)
{
    const int b    = blockIdx.y;
    const int base = blockIdx.x * CHC;
    const int tid  = threadIdx.x;
    const int lane = tid & 31, warp = tid >> 5;

    __shared__ float s_g[4][NG];
    if (tid < NG) {
        float4 q = ((const float4*)gt)[b * NG + tid];
        float hx = q.z * 0.5f, hy = q.w * 0.5f;
        s_g[0][tid] = q.x - hx; s_g[1][tid] = q.y - hy;
        s_g[2][tid] = q.x + hx; s_g[3][tid] = q.y + hy;
    }
    __syncthreads();

    const int a0 = base + tid * TAC;
    uint2  m2 = *(const uint2*)&g_mask[b * NA + a0];
    float4 c2 = ((const float4*)cls)[(b * NA + a0) >> 1];

    float p0 = m2.x ? c2.y : c2.x;
    float p1 = m2.y ? c2.w : c2.z;
    float o0 = 1.f - p0, o1 = 1.f - p1;
    float cls_sum = o0 * o0 * (-logf(p0)) + o1 * o1 * (-logf(p1));

    float crd_sum = 0.f; int cnt = 0;
#pragma unroll
    for (int k = 0; k < TAC; k++) {
        unsigned m = k ? m2.y : m2.x;
        if (m) {
            float4 q = ((const float4*)boxes)[b * NA + a0 + k];
            do {
                int g = __ffs(m) - 1; m &= m - 1;
                crd_sum += fabsf(q.x - s_g[0][g]) + fabsf(q.y - s_g[1][g])
                         + fabsf(q.z - s_g[2][g]) + fabsf(q.w - s_g[3][g]);
                cnt++;
            } while (m);
        }
    }
#pragma unroll
    for (int off = 16; off; off >>= 1) {
        cls_sum += __shfl_down_sync(0xffffffffu, cls_sum, off);
        crd_sum += __shfl_down_sync(0xffffffffu, crd_sum, off);
        cnt     += __shfl_down_sync(0xffffffffu, cnt, off);
    }
    __shared__ float r_cls[8], r_crd[8];
    __shared__ int   r_cnt[8];
    if (lane == 0) { r_cls[warp] = cls_sum; r_crd[warp] = crd_sum; r_cnt[warp] = cnt; }
    __syncthreads();
    if (tid == 0) {
        float tc = 0.f, tr = 0.f; int tn = 0;
#pragma unroll
        for (int w = 0; w < 8; w++) { tc += r_cls[w]; tr += r_crd[w]; tn += r_cnt[w]; }
        atomicAdd(&g_class, tc);
        atomicAdd(&g_coord[b], tr);
        atomicAdd(&g_cnt[b], tn);
        __threadfence();
        if (atomicAdd(&g_tick, 1) == NBLK_C - 1) {   // last block finalizes
            __threadfence();
            float coord = 0.f;
#pragma unroll
            for (int bb = 0; bb < NB; bb++) {
                float c  = *(volatile float*)&g_coord[bb];
                int   nn = *(volatile int*)&g_cnt[bb];
                coord += c / (4.f * (float)nn);
            }
            float cl = (*(volatile float*)&g_class) * (0.01f / 8.f);
            float co = coord * (1.0f / 8.f);
            out[0] = cl + co;
            out[1] = cl;
            out[2] = co;
        }
    }
}

extern "C" void kernel_launch(void* const* d_in, const int* in_sizes, int n_in,
                              void* d_out, int out_size) {
    const float* boxes   = (const float*)d_in[0];   // [8,65536,4]
    const float* classes = (const float*)d_in[1];   // [8,65536,2]
    const float* anchors = (const float*)d_in[2];   // [65536,4]
    const float* gt      = (const float*)d_in[3];   // [8,32,4]
    const int*   nobj    = (const int*)d_in[4];     // [8]
    float* out = (float*)d_out;

    kA<<<dim3(NCH, NB), 256>>>(anchors, gt, nobj);
    kB<<<NB, 256>>>(nobj);
    kC<<<dim3(NCHC, NB), TPB>>>(boxes, classes, gt, out);
}

// round 7
// speedup vs baseline: 1.3787x; 1.3787x over previous
#include <cuda_runtime.h>

#define NB 8
#define NA 65536
#define NG 32

// ---- pass1 (kA) config ----
#define AW   64                // anchors per warp
#define WPB  8                 // warps per block
#define ABLK (AW * WPB)        // 512 anchors per block
#define NCH  (NA / ABLK)       // 128 blocks per batch

// ---- pass2 (kC) config ----
#define TPB 256
#define TAC 2
#define CHC (TPB * TAC)        // 512
#define NCHC (NA / CHC)        // 128
#define NBLK_C (NCHC * NB)     // 1024

// Scratch (no allocations allowed)
__device__ float    g_pi[NB * NG * NCH];     // partial best: inter
__device__ float    g_pu[NB * NG * NCH];     // partial best: union
__device__ unsigned g_px[NB * NG * NCH];     // partial best: anchor idx
__device__ unsigned g_mask[NB * NA];         // bit g set iff valid && iou>0.5 (+forced)
__device__ float    g_class;
__device__ float    g_coord[NB];
__device__ int      g_cnt[NB];
__device__ int      g_tick;

// GSZ lanes per gt-group; G = 32/GSZ anchors processed per warp-pass.
template <int GSZ>
__device__ __forceinline__ void kA_body(
    const float* __restrict__ anchors, const float* __restrict__ gt,
    int n, int b, int blk, int lane, int warp, int tid)
{
    constexpr int G   = 32 / GSZ;
    constexpr int SH  = (GSZ == 8) ? 3 : (GSZ == 16) ? 4 : 5;
    constexpr unsigned MG = (GSZ == 32) ? 0xffffffffu : ((1u << GSZ) - 1u);

    const int gl  = lane & (GSZ - 1);     // this lane's gt
    const int grp = lane >> SH;           // this lane's anchor-group

    // per-lane gt constants
    float gx1, gy1, gx2, gy2, sg;
    {
        float4 q = ((const float4*)gt)[b * NG + gl];    // cx,cy,w,h
        float hx = q.z * 0.5f, hy = q.w * 0.5f;
        gx1 = q.x - hx; gy1 = q.y - hy;
        gx2 = q.x + hx; gy2 = q.y + hy;
        sg  = (gx2 - gx1) * (gy2 - gy1);
        if (gl >= n) {                 // sentinel: zero overlap with any anchor
            gx1 = 3e9f; gx2 = 3e9f; gy1 = 0.f; gy2 = 1.f; sg = 0.f;
        }
    }

    const int wbase = blk * ABLK + warp * AW;

    // 4 independent argmax accumulators (slot k) — no serial select chain
    float    bi[4], bu[4];
    unsigned bx[4];
#pragma unroll
    for (int k = 0; k < 4; k++) { bi[k] = 0.f; bu[k] = 1.f; bx[k] = (unsigned)(wbase + k * G + grp); }

    for (int a = wbase; a < wbase + AW; a += 4 * G) {
        unsigned bals[4];
#pragma unroll
        for (int k = 0; k < 4; k++) {
            const int ak = a + k * G;
            float4 q = __ldg(((const float4*)anchors) + ak + grp);
            float sa = (q.z - q.x) * (q.w - q.y);
            float lx = fmaxf(q.x, gx1), ly = fmaxf(q.y, gy1);
            float rx = fminf(q.z, gx2), ry = fminf(q.w, gy2);
            float w  = fmaxf(rx - lx, 0.f), h = fmaxf(ry - ly, 0.f);
            float inter = w * h;
            float u = (sa + sg) - inter;
            // exact sign of inter - 0.5u (single rounding; 0.5u exact)
            bals[k] = __ballot_sync(0xffffffffu, fmaf(-0.5f, u, inter) > 0.f);
            // iou > best  <=>  inter*bu > bi*u  (u,bu > 0); strict > keeps
            // earliest anchor in this slot's ascending sequence
            if (inter * bu[k] > bi[k] * u) {
                bi[k] = inter; bu[k] = u; bx[k] = (unsigned)(ak + grp);
            }
        }
        if (GSZ == 32) {               // one gt-group: lane0 writes 4 masks at once
            if (lane == 0)
                *(uint4*)&g_mask[b * NA + a] =
                    make_uint4(bals[0], bals[1], bals[2], bals[3]);
        } else {
#pragma unroll
            for (int k = 0; k < 4; k++)
                if (lane < G)
                    g_mask[b * NA + a + k * G + lane] = (bals[k] >> (lane * GSZ)) & MG;
        }
    }

    // merge 4 slots (disjoint anchor sets; explicit index tie-break)
    float Bi = bi[0], Bu = bu[0]; unsigned Bx = bx[0];
#pragma unroll
    for (int k = 1; k < 4; k++) {
        float A = bi[k] * Bu, C = Bi * bu[k];
        if (A > C || (A == C && bx[k] < Bx)) { Bi = bi[k]; Bu = bu[k]; Bx = bx[k]; }
    }

    __shared__ float    s_bi[WPB][32], s_bu[WPB][32];
    __shared__ unsigned s_bx[WPB][32];
    s_bi[warp][lane] = Bi; s_bu[warp][lane] = Bu; s_bx[warp][lane] = Bx;
    __syncthreads();

    if (tid < GSZ) {                   // one thread per g; merge warps × groups
        float Ri = 0.f, Ru = 1.f; unsigned Rx = 0xffffffffu;
#pragma unroll
        for (int w = 0; w < WPB; w++)
#pragma unroll
            for (int j = 0; j < G; j++) {
                float oi = s_bi[w][tid + j * GSZ], ou = s_bu[w][tid + j * GSZ];
                unsigned ox = s_bx[w][tid + j * GSZ];
                float A = oi * Ru, C = Ri * ou;
                if (A > C || (A == C && ox < Rx)) { Ri = oi; Ru = ou; Rx = ox; }
            }
        int p = (b * NG + tid) * NCH + blk;
        g_pi[p] = Ri; g_pu[p] = Ru; g_px[p] = Rx;
    }
}

__global__ __launch_bounds__(256) void kA(
    const float* __restrict__ anchors,   // [A,4] xyxy
    const float* __restrict__ gt,        // [B,G,4] xywh
    const int*   __restrict__ nobj)      // [B]
{
    const int b   = blockIdx.y;
    const int tid = threadIdx.x;
    const int lane = tid & 31, warp = tid >> 5;
    const int n = __ldg(nobj + b);       // uniform per block

    if (n <= 8)
        kA_body<8>(anchors, gt, n, b, blockIdx.x, lane, warp, tid);
    else if (n <= 16)
        kA_body<16>(anchors, gt, n, b, blockIdx.x, lane, warp, tid);
    else
        kA_body<32>(anchors, gt, n, b, blockIdx.x, lane, warp, tid);
}

// ------- Middle: reduce partials -> forced bits; zero accumulators -------
__global__ void kB(const int* __restrict__ nobj) {
    const int b = blockIdx.x;            // 8 blocks x 256 threads
    const int t = threadIdx.x;
    if (b == 0) {
        if (t == 0) { g_class = 0.f; g_tick = 0; }
        if (t < NB) { g_coord[t] = 0.f; g_cnt[t] = 0; }
    }
    const int g = t >> 3, s = t & 7;     // 8 threads per g, 16 chunks each
    float bi = 0.f, bu = 1.f; unsigned bx = 0xffffffffu;
    const int base = (b * NG + g) * NCH;
    for (int c = s * 16; c < s * 16 + 16; c++) {
        float oi = g_pi[base + c], ou = g_pu[base + c]; unsigned ox = g_px[base + c];
        float a = oi * bu, d = bi * ou;
        if (a > d || (a == d && ox < bx)) { bi = oi; bu = ou; bx = ox; }
    }
#pragma unroll
    for (int off = 4; off; off >>= 1) {
        float    oi = __shfl_down_sync(0xffffffffu, bi, off, 8);
        float    ou = __shfl_down_sync(0xffffffffu, bu, off, 8);
        unsigned ox = __shfl_down_sync(0xffffffffu, bx, off, 8);
        float a = oi * bu, d = bi * ou;
        if (a > d || (a == d && ox < bx)) { bi = oi; bu = ou; bx = ox; }
    }
    if (s == 0 && g < nobj[b])
        atomicOr(&g_mask[b * NA + bx], 1u << g);
}

// -------- Pass 2: class + coord losses, ticketed finalize --------
__global__ __launch_bounds__(TPB) void kC(
    const float* __restrict__ boxes,   // [B,A,4]
    const float* __restrict__ cls,     // [B,A,2]
    const float* __restrict__ gt,      // [B,G,4]
    float* __restrict__ out)
{
    const int b    = blockIdx.y;
    const int base = blockIdx.x * CHC;
    const int tid  = threadIdx.x;
    const int lane = tid & 31, warp = tid >> 5;

    __shared__ float s_g[4][NG];
    if (tid < NG) {
        float4 q = ((const float4*)gt)[b * NG + tid];
        float hx = q.z * 0.5f, hy = q.w * 0.5f;
        s_g[0][tid] = q.x - hx; s_g[1][tid] = q.y - hy;
        s_g[2][tid] = q.x + hx; s_g[3][tid] = q.y + hy;
    }
    __syncthreads();

    const int a0 = base + tid * TAC;
    uint2  m2 = *(const uint2*)&g_mask[b * NA + a0];
    float4 c2 = ((const float4*)cls)[(b * NA + a0) >> 1];

    float p0 = m2.x ? c2.y : c2.x;
    float p1 = m2.y ? c2.w : c2.z;
    float o0 = 1.f - p0, o1 = 1.f - p1;
    float cls_sum = o0 * o0 * (-logf(p0)) + o1 * o1 * (-logf(p1));

    float crd_sum = 0.f; int cnt = 0;
#pragma unroll
    for (int k = 0; k < TAC; k++) {
        unsigned m = k ? m2.y : m2.x;
        if (m) {
            float4 q = ((const float4*)boxes)[b * NA + a0 + k];
            do {
                int g = __ffs(m) - 1; m &= m - 1;
                crd_sum += fabsf(q.x - s_g[0][g]) + fabsf(q.y - s_g[1][g])
                         + fabsf(q.z - s_g[2][g]) + fabsf(q.w - s_g[3][g]);
                cnt++;
            } while (m);
        }
    }
#pragma unroll
    for (int off = 16; off; off >>= 1) {
        cls_sum += __shfl_down_sync(0xffffffffu, cls_sum, off);
        crd_sum += __shfl_down_sync(0xffffffffu, crd_sum, off);
        cnt     += __shfl_down_sync(0xffffffffu, cnt, off);
    }
    __shared__ float r_cls[8], r_crd[8];
    __shared__ int   r_cnt[8];
    if (lane == 0) { r_cls[warp] = cls_sum; r_crd[warp] = crd_sum; r_cnt[warp] = cnt; }
    __syncthreads();
    if (tid == 0) {
        float tc = 0.f, tr = 0.f; int tn = 0;
#pragma unroll
        for (int w = 0; w < 8; w++) { tc += r_cls[w]; tr += r_crd[w]; tn += r_cnt[w]; }
        atomicAdd(&g_class, tc);
        atomicAdd(&g_coord[b], tr);
        atomicAdd(&g_cnt[b], tn);
        __threadfence();
        if (atomicAdd(&g_tick, 1) == NBLK_C - 1) {   // last block finalizes
            __threadfence();
            float coord = 0.f;
#pragma unroll
            for (int bb = 0; bb < NB; bb++) {
                float c  = *(volatile float*)&g_coord[bb];
                int   nn = *(volatile int*)&g_cnt[bb];
                coord += c / (4.f * (float)nn);
            }
            float cl = (*(volatile float*)&g_class) * (0.01f / 8.f);
            float co = coord * (1.0f / 8.f);
            out[0] = cl + co;
            out[1] = cl;
            out[2] = co;
        }
    }
}

extern "C" void kernel_launch(void* const* d_in, const int* in_sizes, int n_in,
                              void* d_out, int out_size) {
    const float* boxes   = (const float*)d_in[0];   // [8,65536,4]
    const float* classes = (const float*)d_in[1];   // [8,65536,2]
    const float* anchors = (const float*)d_in[2];   // [65536,4]
    const float* gt      = (const float*)d_in[3];   // [8,32,4]
    const int*   nobj    = (const int*)d_in[4];     // [8]
    float* out = (float*)d_out;

    kA<<<dim3(NCH, NB), 256>>>(anchors, gt, nobj);
    kB<<<NB, 256>>>(nobj);
    kC<<<dim3(NCHC, NB), TPB>>>(boxes, classes, gt, out);
}